// round 14
// baseline (speedup 1.0000x reference)
#include <cuda_runtime.h>
#include <cuda_fp16.h>
#include <math.h>
#include <cstdint>

#define N_TOK 8192
#define DD    1024
#define HH    2048
#define EE    8
#define NA    (N_TOK*2)
#define NA_PAD (NA+128)
#define RBLK  (N_TOK/8)

// ---------------- device scratch ----------------
__device__ float  g_xn [(size_t)N_TOK*DD];
__device__ __half g_xnh[(size_t)N_TOK*DD];
__device__ __half g_h16[(size_t)NA_PAD*HH];
__device__ __half g_w1h[(size_t)EE*HH*DD];
__device__ __half g_w2h[(size_t)EE*DD*HH];
__device__ __half g_zero[HH];                   // zero-initialized
__device__ float  g_y[(size_t)NA*DD];
__device__ float  g_gate[NA];
__device__ int    g_eid[NA];
__device__ int    g_counts[EE], g_offsets[EE], g_cursor[EE];
__device__ int    g_rows[NA];
__device__ float  g_partials[RBLK*EE];

// ---------------- helpers ----------------
__device__ __forceinline__ uint32_t smem_u32(const void* p) {
    uint32_t a;
    asm("{ .reg .u64 t; cvta.to.shared.u64 t, %1; cvt.u32.u64 %0, t; }" : "=r"(a) : "l"(p));
    return a;
}
__device__ __forceinline__ void ldmx4(uint32_t* r, uint32_t addr) {
    asm volatile("ldmatrix.sync.aligned.m8n8.x4.shared.b16 {%0,%1,%2,%3}, [%4];"
        : "=r"(r[0]), "=r"(r[1]), "=r"(r[2]), "=r"(r[3]) : "r"(addr));
}
__device__ __forceinline__ void mma16816h(float* d, const uint32_t* a, const uint32_t* b) {
    asm volatile("mma.sync.aligned.m16n8k16.row.col.f32.f16.f16.f32 "
        "{%0,%1,%2,%3}, {%4,%5,%6,%7}, {%8,%9}, {%0,%1,%2,%3};"
        : "+f"(d[0]), "+f"(d[1]), "+f"(d[2]), "+f"(d[3])
        : "r"(a[0]), "r"(a[1]), "r"(a[2]), "r"(a[3]), "r"(b[0]), "r"(b[1]));
}
__device__ __forceinline__ uint32_t rnpackh(float fx, float fy) {
    uint32_t r;
    asm("cvt.rn.f16x2.f32 %0, %1, %2;" : "=r"(r) : "f"(fy), "f"(fx));
    return r;
}
#define CPA16(dst, src) asm volatile("cp.async.cg.shared.global [%0], [%1], 16;" :: "r"(dst), "l"(src))
#define CPA_COMMIT()    asm volatile("cp.async.commit_group;" ::: "memory")
#define CPA_WAIT1()     asm volatile("cp.async.wait_group 1;" ::: "memory")
#define CPA_WAIT0()     asm volatile("cp.async.wait_group 0;" ::: "memory")
__device__ __forceinline__ float gelu_exact(float v) {
    return 0.5f * v * (1.0f + erff(v * 0.70710678118654752f));
}

// ---------------- small kernels ----------------
__global__ void init_kernel() {
    int t = threadIdx.x;
    if (t < EE) { g_counts[t] = 0; g_cursor[t] = 0; }
}

__global__ void ln_kernel(const float* __restrict__ x,
                          const float* __restrict__ gamma,
                          const float* __restrict__ beta) {
    int t = blockIdx.x, tid = threadIdx.x;
    const float4* xr = (const float4*)(x + (size_t)t * DD);
    float4 v = xr[tid];
    float s = v.x + v.y + v.z + v.w;
    float ss = fmaf(v.x, v.x, fmaf(v.y, v.y, fmaf(v.z, v.z, v.w * v.w)));
    #pragma unroll
    for (int o = 16; o > 0; o >>= 1) {
        s  += __shfl_xor_sync(0xffffffffu, s,  o);
        ss += __shfl_xor_sync(0xffffffffu, ss, o);
    }
    __shared__ float shs[8], shss[8];
    int warp = tid >> 5, lane = tid & 31;
    if (lane == 0) { shs[warp] = s; shss[warp] = ss; }
    __syncthreads();
    __shared__ float mu_s, rstd_s;
    if (tid == 0) {
        float S = 0.f, SS = 0.f;
        #pragma unroll
        for (int w = 0; w < 8; w++) { S += shs[w]; SS += shss[w]; }
        float mu = S / (float)DD;
        mu_s = mu; rstd_s = rsqrtf(SS / (float)DD - mu * mu + 1e-5f);
    }
    __syncthreads();
    float mu = mu_s, rstd = rstd_s;
    float4 gv = ((const float4*)gamma)[tid];
    float4 bv = ((const float4*)beta)[tid];
    float4 o;
    o.x = (v.x - mu) * rstd * gv.x + bv.x;
    o.y = (v.y - mu) * rstd * gv.y + bv.y;
    o.z = (v.z - mu) * rstd * gv.z + bv.z;
    o.w = (v.w - mu) * rstd * gv.w + bv.w;
    ((float4*)(g_xn + (size_t)t * DD))[tid] = o;
    uint2 hp;
    hp.x = rnpackh(o.x, o.y);
    hp.y = rnpackh(o.z, o.w);
    *(uint2*)(g_xnh + (size_t)t * DD + tid * 4) = hp;
}

// fp32 -> fp16 weights (one float4 per thread)
__global__ void convh_kernel(const float* __restrict__ src, __half* __restrict__ dst) {
    size_t i = (size_t)blockIdx.x * 256 + threadIdx.x;
    float4 v = ((const float4*)src)[i];
    uint2 hp;
    hp.x = rnpackh(v.x, v.y);
    hp.y = rnpackh(v.z, v.w);
    *(uint2*)(dst + i * 4) = hp;
}

__global__ void router_kernel(const float* __restrict__ gate_w) {
    __shared__ float gw[EE * DD];
    __shared__ float probs_sh[8][EE];
    int tid = threadIdx.x;
    #pragma unroll
    for (int p = 0; p < 8; p++)
        ((float4*)gw)[tid + p * 256] = ((const float4*)gate_w)[tid + p * 256];
    __syncthreads();
    int warp = tid >> 5, lane = tid & 31;
    int t = blockIdx.x * 8 + warp;
    const float4* xr = (const float4*)(g_xn + (size_t)t * DD);
    float acc[EE];
    #pragma unroll
    for (int e = 0; e < EE; e++) acc[e] = 0.f;
    #pragma unroll
    for (int c = 0; c < 8; c++) {
        float4 xv = xr[c * 32 + lane];
        #pragma unroll
        for (int e = 0; e < EE; e++) {
            float4 gv = ((const float4*)(gw + e * DD))[c * 32 + lane];
            acc[e] += xv.x * gv.x + xv.y * gv.y + xv.z * gv.z + xv.w * gv.w;
        }
    }
    #pragma unroll
    for (int o = 16; o > 0; o >>= 1)
        #pragma unroll
        for (int e = 0; e < EE; e++)
            acc[e] += __shfl_xor_sync(0xffffffffu, acc[e], o);
    if (lane == 0) {
        int i0 = 0; float v0 = acc[0];
        #pragma unroll
        for (int e = 1; e < EE; e++) if (acc[e] > v0) { v0 = acc[e]; i0 = e; }
        int i1 = -1; float v1 = -3.4e38f;
        #pragma unroll
        for (int e = 0; e < EE; e++) if (e != i0 && acc[e] > v1) { v1 = acc[e]; i1 = e; }
        float e10 = expf(v1 - v0);
        g_eid[2*t] = i0; g_eid[2*t+1] = i1;
        g_gate[2*t] = 1.f / (1.f + e10); g_gate[2*t+1] = e10 / (1.f + e10);
        atomicAdd(&g_counts[i0], 1);
        atomicAdd(&g_counts[i1], 1);
        float s = 0.f, p[EE];
        #pragma unroll
        for (int e = 0; e < EE; e++) { p[e] = expf(acc[e] - v0); s += p[e]; }
        float inv = 1.f / s;
        #pragma unroll
        for (int e = 0; e < EE; e++) probs_sh[warp][e] = p[e] * inv;
    }
    __syncthreads();
    if (tid < EE) {
        float s = 0.f;
        #pragma unroll
        for (int w = 0; w < 8; w++) s += probs_sh[w][tid];
        g_partials[blockIdx.x * EE + tid] = s;
    }
}

__global__ void finalize_kernel(float* __restrict__ d_out, int has_scalar) {
    __shared__ float avg[EE];
    int tid = threadIdx.x;
    int e = tid >> 5, lane = tid & 31;
    float s = 0.f;
    for (int b = lane; b < RBLK; b += 32) s += g_partials[b * EE + e];
    #pragma unroll
    for (int o = 16; o > 0; o >>= 1) s += __shfl_xor_sync(0xffffffffu, s, o);
    if (lane == 0) avg[e] = s / (float)N_TOK;
    __syncthreads();
    if (tid == 0) {
        int o = 0;
        #pragma unroll
        for (int q = 0; q < EE; q++) { g_offsets[q] = o; o += g_counts[q]; }
        if (has_scalar) {
            float m = 0.f;
            #pragma unroll
            for (int q = 0; q < EE; q++) m += avg[q];
            m /= (float)EE;
            float v = 0.f;
            #pragma unroll
            for (int q = 0; q < EE; q++) { float d = avg[q] - m; v += d * d; }
            v /= (float)(EE - 1);
            float r = sqrtf(v) / (m + 1e-6f);
            d_out[(size_t)N_TOK * DD] = r * r * 0.01f;
        }
    }
}

__global__ void place_kernel() {
    int a = blockIdx.x * 256 + threadIdx.x;
    if (a >= NA) return;
    int e = g_eid[a];
    int pos = atomicAdd(&g_cursor[e], 1);
    g_rows[g_offsets[e] + pos] = a;
}

// ---- grouped GEMM: fp16 operands in GMEM, cp.async 2-stage, ldmatrix+HMMA ----
#define RSB 80             // bytes per 32-col fp16 row (64B data + 16B pad)
#define APL (128*RSB)      // 10240 bytes per plane
#define STGB (2*APL)       // A + B planes per stage = 20480
// 2 stages = 40960 B static smem

// MODE 0: gemm1  A = gathered g_xnh rows, B = g_w1h, out = gelu -> g_h16 (fp16)
// MODE 1: gemm2  A = g_h16 rows,          B = g_w2h, out = gate*acc -> g_y
template<int KTOT, int NROWS, int MODE>
__global__ __launch_bounds__(512)
void gemm_kernel(const __half* __restrict__ Wh) {
    int e = blockIdx.z;
    int cnt = g_counts[e];
    int m0 = blockIdx.y * 128;
    if (m0 >= cnt) return;
    int off = g_offsets[e];
    int n0 = blockIdx.x * 128;

    __shared__ __align__(16) char smem[2 * STGB];
    __shared__ const __half* rowp[128];

    int tid = threadIdx.x, wid = tid >> 5, lane = tid & 31;
    int wm = wid >> 2, wn = wid & 3;          // 4x4 warp grid, warp tile 32x32
    int g = lane >> 2, ttg = lane & 3;

    if (tid < 128) {
        int r = m0 + tid;
        const __half* p = g_zero;
        if (r < cnt) {
            if (MODE == 0) {
                int aid = g_rows[off + r];
                p = g_xnh + (size_t)(aid >> 1) * DD;
            } else {
                p = g_h16 + (size_t)(off + r) * (size_t)KTOT;
            }
        }
        rowp[tid] = p;
    }
    __syncthreads();

    const __half* Bbase = Wh + ((size_t)e * NROWS + n0) * (size_t)KTOT;
    uint32_t sb = smem_u32(smem);

    uint32_t a_off = (uint32_t)((wm * 32 + (lane & 15)) * RSB + (lane >> 4) * 16);
    uint32_t b_off = (uint32_t)(APL +
        (wn * 32 + ((lane >> 4) << 3) + (lane & 7)) * RSB + ((lane >> 3) & 1) * 16);

    // staging: 2 cp.async 16B per thread; A = idx<512, B = idx>=512; 4 x 16B per row
    int srow[2], sc16[2], sIsA[2];
    #pragma unroll
    for (int q = 0; q < 2; q++) {
        int idx = q * 512 + tid;
        int rem = idx & 511;
        srow[q] = rem >> 2;
        sc16[q] = (rem & 3);       // 16B unit within row
        sIsA[q] = (idx < 512);
    }

    float acc[2][4][4];
    #pragma unroll
    for (int a = 0; a < 2; a++)
        #pragma unroll
        for (int b = 0; b < 4; b++)
            #pragma unroll
            for (int c = 0; c < 4; c++) acc[a][b][c] = 0.f;

    const int NCH = KTOT / 32;
    // prologue: load chunks 0 and 1
    #pragma unroll
    for (int s = 0; s < 2; s++) {
        #pragma unroll
        for (int q = 0; q < 2; q++) {
            const __half* src = (sIsA[q] ? rowp[srow[q]] : Bbase + (size_t)srow[q] * KTOT)
                                + s * 32 + sc16[q] * 8;
            uint32_t dst = sb + s * STGB + (sIsA[q] ? 0 : APL)
                         + (uint32_t)(srow[q] * RSB + sc16[q] * 16);
            CPA16(dst, src);
        }
        CPA_COMMIT();
    }

    for (int c = 0; c < NCH; c++) {
        CPA_WAIT1();
        __syncthreads();
        // ---- compute chunk c from stage c&1: 2 k16 steps ----
        uint32_t st = sb + (c & 1) * STGB;
        #pragma unroll
        for (int ks = 0; ks < 2; ks++) {
            uint32_t ah[2][4], bh[4][2];
            #pragma unroll
            for (int mt = 0; mt < 2; mt++)
                ldmx4(ah[mt], st + a_off + mt * (16 * RSB) + ks * 32);
            #pragma unroll
            for (int p = 0; p < 2; p++) {
                uint32_t r[4];
                ldmx4(r, st + b_off + p * (16 * RSB) + ks * 32);
                bh[2*p][0] = r[0]; bh[2*p][1] = r[1];
                bh[2*p+1][0] = r[2]; bh[2*p+1][1] = r[3];
            }
            #pragma unroll
            for (int mt = 0; mt < 2; mt++)
                #pragma unroll
                for (int nt = 0; nt < 4; nt++)
                    mma16816h(acc[mt][nt], ah[mt], bh[nt]);
        }
        __syncthreads();
        // ---- issue cp.async for chunk c+2 into the stage just freed ----
        if (c + 2 < NCH) {
            int k0n = (c + 2) * 32;
            #pragma unroll
            for (int q = 0; q < 2; q++) {
                const __half* src = (sIsA[q] ? rowp[srow[q]] : Bbase + (size_t)srow[q] * KTOT)
                                    + k0n + sc16[q] * 8;
                uint32_t dst = sb + (c & 1) * STGB + (sIsA[q] ? 0 : APL)
                             + (uint32_t)(srow[q] * RSB + sc16[q] * 16);
                CPA16(dst, src);
            }
        }
        CPA_COMMIT();
    }
    CPA_WAIT0();

    // ---- epilogue ----
    int t2 = ttg * 2;
    #pragma unroll
    for (int mt = 0; mt < 2; mt++) {
        int r0 = m0 + wm * 32 + mt * 16 + g;
        int r1 = r0 + 8;
        bool v0 = r0 < cnt, v1 = r1 < cnt;
        float gate0 = 0.f, gate1 = 0.f;
        int aid0 = 0, aid1 = 0;
        if (MODE == 1) {
            if (v0) { aid0 = g_rows[off + r0]; gate0 = g_gate[aid0]; }
            if (v1) { aid1 = g_rows[off + r1]; gate1 = g_gate[aid1]; }
        }
        #pragma unroll
        for (int nt = 0; nt < 4; nt++) {
            int col = n0 + wn * 32 + nt * 8 + t2;
            float c0 = acc[mt][nt][0], c1 = acc[mt][nt][1];
            float c2 = acc[mt][nt][2], c3 = acc[mt][nt][3];
            if (MODE == 0) {
                if (v0)
                    *(uint32_t*)(g_h16 + (size_t)(off + r0) * HH + col)
                        = rnpackh(gelu_exact(c0), gelu_exact(c1));
                if (v1)
                    *(uint32_t*)(g_h16 + (size_t)(off + r1) * HH + col)
                        = rnpackh(gelu_exact(c2), gelu_exact(c3));
            } else {
                if (v0) {
                    float2 o; o.x = c0 * gate0; o.y = c1 * gate0;
                    *(float2*)(g_y + (size_t)aid0 * DD + col) = o;
                }
                if (v1) {
                    float2 o; o.x = c2 * gate1; o.y = c3 * gate1;
                    *(float2*)(g_y + (size_t)aid1 * DD + col) = o;
                }
            }
        }
    }
}

// ---------------- combine ----------------
__global__ void combine_kernel(const float* __restrict__ x, float* __restrict__ out) {
    size_t idx = (size_t)blockIdx.x * 256 + threadIdx.x;
    int t = (int)(idx / (DD / 4));
    int dv = (int)(idx % (DD / 4));
    float4 xv = ((const float4*)x)[idx];
    float4 y0 = ((const float4*)(g_y + (size_t)(2 * t)     * DD))[dv];
    float4 y1 = ((const float4*)(g_y + (size_t)(2 * t + 1) * DD))[dv];
    float4 o;
    o.x = xv.x + y0.x + y1.x;
    o.y = xv.y + y0.y + y1.y;
    o.z = xv.z + y0.z + y1.z;
    o.w = xv.w + y0.w + y1.w;
    ((float4*)out)[idx] = o;
}

// ---------------- launch ----------------
extern "C" void kernel_launch(void* const* d_in, const int* in_sizes, int n_in,
                              void* d_out, int out_size) {
    const float* x      = (const float*)d_in[0];
    const float* gate_w = (const float*)d_in[1];
    const float* w1     = (const float*)d_in[2];
    const float* w2     = (const float*)d_in[3];
    const float* gamma  = (const float*)d_in[4];
    const float* beta   = (const float*)d_in[5];
    float* out = (float*)d_out;
    int has_scalar = (out_size > N_TOK * DD) ? 1 : 0;

    init_kernel    <<<1, 32>>>();
    ln_kernel      <<<N_TOK, 256>>>(x, gamma, beta);
    convh_kernel   <<<(EE*(size_t)HH*DD/4)/256, 256>>>(w1, g_w1h);
    convh_kernel   <<<(EE*(size_t)DD*HH/4)/256, 256>>>(w2, g_w2h);
    router_kernel  <<<RBLK, 256>>>(gate_w);
    finalize_kernel<<<1, 256>>>(out, has_scalar);
    place_kernel   <<<NA / 256, 256>>>();
    gemm_kernel<DD, HH, 0><<<dim3(HH / 128, 128, EE), 512>>>(g_w1h);
    gemm_kernel<HH, DD, 1><<<dim3(DD / 128, 128, EE), 512>>>(g_w2h);
    combine_kernel <<<(N_TOK * (DD / 4)) / 256, 256>>>(x, out);
}

// round 15
// speedup vs baseline: 1.8525x; 1.8525x over previous
#include <cuda_runtime.h>
#include <cuda_fp16.h>
#include <math.h>
#include <cstdint>

#define N_TOK 8192
#define DD    1024
#define HH    2048
#define EE    8
#define NA    (N_TOK*2)
#define NA_PAD (NA+128)
#define RBLK  (N_TOK/8)

// ---------------- device scratch ----------------
__device__ float  g_xn [(size_t)N_TOK*DD];
__device__ __half g_xnh[(size_t)N_TOK*DD];
__device__ __half g_h16[(size_t)NA_PAD*HH];
__device__ __half g_w1h[(size_t)EE*HH*DD];
__device__ __half g_w2h[(size_t)EE*DD*HH];
__device__ float  g_y[(size_t)NA*DD];
__device__ float  g_gate[NA];
__device__ int    g_eid[NA];
__device__ int    g_counts[EE], g_offsets[EE], g_cursor[EE];
__device__ int    g_rows[NA];
__device__ float  g_partials[RBLK*EE];

// ---------------- helpers ----------------
__device__ __forceinline__ uint32_t smem_u32(const void* p) {
    uint32_t a;
    asm("{ .reg .u64 t; cvta.to.shared.u64 t, %1; cvt.u32.u64 %0, t; }" : "=r"(a) : "l"(p));
    return a;
}
__device__ __forceinline__ void ldmx4(uint32_t* r, uint32_t addr) {
    asm volatile("ldmatrix.sync.aligned.m8n8.x4.shared.b16 {%0,%1,%2,%3}, [%4];"
        : "=r"(r[0]), "=r"(r[1]), "=r"(r[2]), "=r"(r[3]) : "r"(addr));
}
__device__ __forceinline__ void mma16816h(float* d, const uint32_t* a, const uint32_t* b) {
    asm volatile("mma.sync.aligned.m16n8k16.row.col.f32.f16.f16.f32 "
        "{%0,%1,%2,%3}, {%4,%5,%6,%7}, {%8,%9}, {%0,%1,%2,%3};"
        : "+f"(d[0]), "+f"(d[1]), "+f"(d[2]), "+f"(d[3])
        : "r"(a[0]), "r"(a[1]), "r"(a[2]), "r"(a[3]), "r"(b[0]), "r"(b[1]));
}
__device__ __forceinline__ uint32_t rnpackh(float fx, float fy) {
    uint32_t r;
    asm("cvt.rn.f16x2.f32 %0, %1, %2;" : "=r"(r) : "f"(fy), "f"(fx));
    return r;
}
__device__ __forceinline__ float gelu_exact(float v) {
    return 0.5f * v * (1.0f + erff(v * 0.70710678118654752f));
}

// ---------------- small kernels ----------------
__global__ void init_kernel() {
    int t = threadIdx.x;
    if (t < EE) { g_counts[t] = 0; g_cursor[t] = 0; }
}

__global__ void ln_kernel(const float* __restrict__ x,
                          const float* __restrict__ gamma,
                          const float* __restrict__ beta) {
    int t = blockIdx.x, tid = threadIdx.x;
    const float4* xr = (const float4*)(x + (size_t)t * DD);
    float4 v = xr[tid];
    float s = v.x + v.y + v.z + v.w;
    float ss = fmaf(v.x, v.x, fmaf(v.y, v.y, fmaf(v.z, v.z, v.w * v.w)));
    #pragma unroll
    for (int o = 16; o > 0; o >>= 1) {
        s  += __shfl_xor_sync(0xffffffffu, s,  o);
        ss += __shfl_xor_sync(0xffffffffu, ss, o);
    }
    __shared__ float shs[8], shss[8];
    int warp = tid >> 5, lane = tid & 31;
    if (lane == 0) { shs[warp] = s; shss[warp] = ss; }
    __syncthreads();
    __shared__ float mu_s, rstd_s;
    if (tid == 0) {
        float S = 0.f, SS = 0.f;
        #pragma unroll
        for (int w = 0; w < 8; w++) { S += shs[w]; SS += shss[w]; }
        float mu = S / (float)DD;
        mu_s = mu; rstd_s = rsqrtf(SS / (float)DD - mu * mu + 1e-5f);
    }
    __syncthreads();
    float mu = mu_s, rstd = rstd_s;
    float4 gv = ((const float4*)gamma)[tid];
    float4 bv = ((const float4*)beta)[tid];
    float4 o;
    o.x = (v.x - mu) * rstd * gv.x + bv.x;
    o.y = (v.y - mu) * rstd * gv.y + bv.y;
    o.z = (v.z - mu) * rstd * gv.z + bv.z;
    o.w = (v.w - mu) * rstd * gv.w + bv.w;
    ((float4*)(g_xn + (size_t)t * DD))[tid] = o;
    uint2 hp;
    hp.x = rnpackh(o.x, o.y);
    hp.y = rnpackh(o.z, o.w);
    *(uint2*)(g_xnh + (size_t)t * DD + tid * 4) = hp;
}

// fp32 -> fp16 weights (one float4 per thread)
__global__ void convh_kernel(const float* __restrict__ src, __half* __restrict__ dst) {
    size_t i = (size_t)blockIdx.x * 256 + threadIdx.x;
    float4 v = ((const float4*)src)[i];
    uint2 hp;
    hp.x = rnpackh(v.x, v.y);
    hp.y = rnpackh(v.z, v.w);
    *(uint2*)(dst + i * 4) = hp;
}

__global__ void router_kernel(const float* __restrict__ gate_w) {
    __shared__ float gw[EE * DD];
    __shared__ float probs_sh[8][EE];
    int tid = threadIdx.x;
    #pragma unroll
    for (int p = 0; p < 8; p++)
        ((float4*)gw)[tid + p * 256] = ((const float4*)gate_w)[tid + p * 256];
    __syncthreads();
    int warp = tid >> 5, lane = tid & 31;
    int t = blockIdx.x * 8 + warp;
    const float4* xr = (const float4*)(g_xn + (size_t)t * DD);
    float acc[EE];
    #pragma unroll
    for (int e = 0; e < EE; e++) acc[e] = 0.f;
    #pragma unroll
    for (int c = 0; c < 8; c++) {
        float4 xv = xr[c * 32 + lane];
        #pragma unroll
        for (int e = 0; e < EE; e++) {
            float4 gv = ((const float4*)(gw + e * DD))[c * 32 + lane];
            acc[e] += xv.x * gv.x + xv.y * gv.y + xv.z * gv.z + xv.w * gv.w;
        }
    }
    #pragma unroll
    for (int o = 16; o > 0; o >>= 1)
        #pragma unroll
        for (int e = 0; e < EE; e++)
            acc[e] += __shfl_xor_sync(0xffffffffu, acc[e], o);
    if (lane == 0) {
        int i0 = 0; float v0 = acc[0];
        #pragma unroll
        for (int e = 1; e < EE; e++) if (acc[e] > v0) { v0 = acc[e]; i0 = e; }
        int i1 = -1; float v1 = -3.4e38f;
        #pragma unroll
        for (int e = 0; e < EE; e++) if (e != i0 && acc[e] > v1) { v1 = acc[e]; i1 = e; }
        float e10 = expf(v1 - v0);
        g_eid[2*t] = i0; g_eid[2*t+1] = i1;
        g_gate[2*t] = 1.f / (1.f + e10); g_gate[2*t+1] = e10 / (1.f + e10);
        atomicAdd(&g_counts[i0], 1);
        atomicAdd(&g_counts[i1], 1);
        float s = 0.f, p[EE];
        #pragma unroll
        for (int e = 0; e < EE; e++) { p[e] = expf(acc[e] - v0); s += p[e]; }
        float inv = 1.f / s;
        #pragma unroll
        for (int e = 0; e < EE; e++) probs_sh[warp][e] = p[e] * inv;
    }
    __syncthreads();
    if (tid < EE) {
        float s = 0.f;
        #pragma unroll
        for (int w = 0; w < 8; w++) s += probs_sh[w][tid];
        g_partials[blockIdx.x * EE + tid] = s;
    }
}

__global__ void finalize_kernel(float* __restrict__ d_out, int has_scalar) {
    __shared__ float avg[EE];
    int tid = threadIdx.x;
    int e = tid >> 5, lane = tid & 31;
    float s = 0.f;
    for (int b = lane; b < RBLK; b += 32) s += g_partials[b * EE + e];
    #pragma unroll
    for (int o = 16; o > 0; o >>= 1) s += __shfl_xor_sync(0xffffffffu, s, o);
    if (lane == 0) avg[e] = s / (float)N_TOK;
    __syncthreads();
    if (tid == 0) {
        int o = 0;
        #pragma unroll
        for (int q = 0; q < EE; q++) { g_offsets[q] = o; o += g_counts[q]; }
        if (has_scalar) {
            float m = 0.f;
            #pragma unroll
            for (int q = 0; q < EE; q++) m += avg[q];
            m /= (float)EE;
            float v = 0.f;
            #pragma unroll
            for (int q = 0; q < EE; q++) { float d = avg[q] - m; v += d * d; }
            v /= (float)(EE - 1);
            float r = sqrtf(v) / (m + 1e-6f);
            d_out[(size_t)N_TOK * DD] = r * r * 0.01f;
        }
    }
}

__global__ void place_kernel() {
    int a = blockIdx.x * 256 + threadIdx.x;
    if (a >= NA) return;
    int e = g_eid[a];
    int pos = atomicAdd(&g_cursor[e], 1);
    g_rows[g_offsets[e] + pos] = a;
}

// ---- grouped GEMM: fp16 GMEM operands, R13 loop (LDG reg prefetch + STS.128) ----
#define RSB 80             // bytes per 32-col fp16 row (64B data + 16B pad)
#define APL (128*RSB)      // 10240 bytes per plane
// planes: [A][B] = 2*APL = 20480 B

// MODE 0: gemm1  A = gathered g_xnh rows, B = g_w1h, out = gelu -> g_h16 (fp16)
// MODE 1: gemm2  A = g_h16 rows,          B = g_w2h, out = gate*acc -> g_y
template<int KTOT, int NROWS, int MODE>
__global__ __launch_bounds__(512)
void gemm_kernel(const __half* __restrict__ Wh) {
    int e = blockIdx.z;
    int cnt = g_counts[e];
    int m0 = blockIdx.y * 128;
    if (m0 >= cnt) return;
    int off = g_offsets[e];
    int n0 = blockIdx.x * 128;

    __shared__ __align__(16) char smem[2 * APL];
    __shared__ const __half* rowp[128];

    int tid = threadIdx.x, wid = tid >> 5, lane = tid & 31;
    int wm = wid >> 2, wn = wid & 3;          // 4x4 warp grid, warp tile 32x32
    int g = lane >> 2, ttg = lane & 3;

    if (tid < 128) {
        int r = m0 + tid;
        const __half* p = nullptr;
        if (r < cnt) {
            if (MODE == 0) {
                int aid = g_rows[off + r];
                p = g_xnh + (size_t)(aid >> 1) * DD;
            } else {
                p = g_h16 + (size_t)(off + r) * (size_t)KTOT;
            }
        }
        rowp[tid] = p;
    }
    __syncthreads();

    const __half* Bbase = Wh + ((size_t)e * NROWS + n0) * (size_t)KTOT;
    uint32_t sb = smem_u32(smem);

    uint32_t a_addr = sb + (uint32_t)((wm * 32 + (lane & 15)) * RSB + (lane >> 4) * 16);
    uint32_t b_addr = sb + APL +
        (uint32_t)((wn * 32 + ((lane >> 4) << 3) + (lane & 7)) * RSB + ((lane >> 3) & 1) * 16);

    // staging: 2 uint4 (16B = 8 halves) per thread; A: idx<512, B: idx>=512; 4 units/row
    int srow[2], sc16[2], sIsA[2];
    #pragma unroll
    for (int q = 0; q < 2; q++) {
        int idx = q * 512 + tid;
        int rem = idx & 511;
        srow[q] = rem >> 2;
        sc16[q] = rem & 3;
        sIsA[q] = (idx < 512);
    }

    float acc[2][4][4];
    #pragma unroll
    for (int a = 0; a < 2; a++)
        #pragma unroll
        for (int b = 0; b < 4; b++)
            #pragma unroll
            for (int c = 0; c < 4; c++) acc[a][b][c] = 0.f;

    // ---- prefetch chunk 0 into registers ----
    uint4 pref[2];
    #pragma unroll
    for (int q = 0; q < 2; q++) {
        if (sIsA[q]) {
            const __half* p = rowp[srow[q]];
            pref[q] = p ? *(const uint4*)(p + sc16[q] * 8) : make_uint4(0u, 0u, 0u, 0u);
        } else {
            pref[q] = *(const uint4*)(Bbase + (size_t)srow[q] * KTOT + sc16[q] * 8);
        }
    }

    const int NCH = KTOT / 32;
    for (int c = 0; c < NCH; c++) {
        // ---- store prefetched regs -> fp16 planes ----
        #pragma unroll
        for (int q = 0; q < 2; q++) {
            char* pl = smem + (sIsA[q] ? 0 : APL);
            *(uint4*)(pl + srow[q] * RSB + sc16[q] * 16) = pref[q];
        }
        __syncthreads();

        // ---- issue next chunk's global loads (latency hidden by mma below) ----
        if (c + 1 < NCH) {
            int k0n = (c + 1) * 32;
            #pragma unroll
            for (int q = 0; q < 2; q++) {
                if (sIsA[q]) {
                    const __half* p = rowp[srow[q]];
                    pref[q] = p ? *(const uint4*)(p + k0n + sc16[q] * 8)
                                : make_uint4(0u, 0u, 0u, 0u);
                } else {
                    pref[q] = *(const uint4*)(Bbase + (size_t)srow[q] * KTOT + k0n + sc16[q] * 8);
                }
            }
        }

        // ---- compute: 2 k16 steps from smem ----
        #pragma unroll
        for (int ks = 0; ks < 2; ks++) {
            uint32_t ah[2][4], bh[4][2];
            #pragma unroll
            for (int mt = 0; mt < 2; mt++)
                ldmx4(ah[mt], a_addr + mt * (16 * RSB) + ks * 32);
            #pragma unroll
            for (int p = 0; p < 2; p++) {
                uint32_t r[4];
                ldmx4(r, b_addr + p * (16 * RSB) + ks * 32);
                bh[2*p][0] = r[0]; bh[2*p][1] = r[1];
                bh[2*p+1][0] = r[2]; bh[2*p+1][1] = r[3];
            }
            #pragma unroll
            for (int mt = 0; mt < 2; mt++)
                #pragma unroll
                for (int nt = 0; nt < 4; nt++)
                    mma16816h(acc[mt][nt], ah[mt], bh[nt]);
        }
        __syncthreads();
    }

    // ---- epilogue ----
    int t2 = ttg * 2;
    #pragma unroll
    for (int mt = 0; mt < 2; mt++) {
        int r0 = m0 + wm * 32 + mt * 16 + g;
        int r1 = r0 + 8;
        bool v0 = r0 < cnt, v1 = r1 < cnt;
        float gate0 = 0.f, gate1 = 0.f;
        int aid0 = 0, aid1 = 0;
        if (MODE == 1) {
            if (v0) { aid0 = g_rows[off + r0]; gate0 = g_gate[aid0]; }
            if (v1) { aid1 = g_rows[off + r1]; gate1 = g_gate[aid1]; }
        }
        #pragma unroll
        for (int nt = 0; nt < 4; nt++) {
            int col = n0 + wn * 32 + nt * 8 + t2;
            float c0 = acc[mt][nt][0], c1 = acc[mt][nt][1];
            float c2 = acc[mt][nt][2], c3 = acc[mt][nt][3];
            if (MODE == 0) {
                if (v0)
                    *(uint32_t*)(g_h16 + (size_t)(off + r0) * HH + col)
                        = rnpackh(gelu_exact(c0), gelu_exact(c1));
                if (v1)
                    *(uint32_t*)(g_h16 + (size_t)(off + r1) * HH + col)
                        = rnpackh(gelu_exact(c2), gelu_exact(c3));
            } else {
                if (v0) {
                    float2 o; o.x = c0 * gate0; o.y = c1 * gate0;
                    *(float2*)(g_y + (size_t)aid0 * DD + col) = o;
                }
                if (v1) {
                    float2 o; o.x = c2 * gate1; o.y = c3 * gate1;
                    *(float2*)(g_y + (size_t)aid1 * DD + col) = o;
                }
            }
        }
    }
}

// ---------------- combine ----------------
__global__ void combine_kernel(const float* __restrict__ x, float* __restrict__ out) {
    size_t idx = (size_t)blockIdx.x * 256 + threadIdx.x;
    int t = (int)(idx / (DD / 4));
    int dv = (int)(idx % (DD / 4));
    float4 xv = ((const float4*)x)[idx];
    float4 y0 = ((const float4*)(g_y + (size_t)(2 * t)     * DD))[dv];
    float4 y1 = ((const float4*)(g_y + (size_t)(2 * t + 1) * DD))[dv];
    float4 o;
    o.x = xv.x + y0.x + y1.x;
    o.y = xv.y + y0.y + y1.y;
    o.z = xv.z + y0.z + y1.z;
    o.w = xv.w + y0.w + y1.w;
    ((float4*)out)[idx] = o;
}

// ---------------- launch ----------------
extern "C" void kernel_launch(void* const* d_in, const int* in_sizes, int n_in,
                              void* d_out, int out_size) {
    const float* x      = (const float*)d_in[0];
    const float* gate_w = (const float*)d_in[1];
    const float* w1     = (const float*)d_in[2];
    const float* w2     = (const float*)d_in[3];
    const float* gamma  = (const float*)d_in[4];
    const float* beta   = (const float*)d_in[5];
    float* out = (float*)d_out;
    int has_scalar = (out_size > N_TOK * DD) ? 1 : 0;

    init_kernel    <<<1, 32>>>();
    ln_kernel      <<<N_TOK, 256>>>(x, gamma, beta);
    convh_kernel   <<<(EE*(size_t)HH*DD/4)/256, 256>>>(w1, g_w1h);
    convh_kernel   <<<(EE*(size_t)DD*HH/4)/256, 256>>>(w2, g_w2h);
    router_kernel  <<<RBLK, 256>>>(gate_w);
    finalize_kernel<<<1, 256>>>(out, has_scalar);
    place_kernel   <<<NA / 256, 256>>>();
    gemm_kernel<DD, HH, 0><<<dim3(HH / 128, 128, EE), 512>>>(g_w1h);
    gemm_kernel<HH, DD, 1><<<dim3(DD / 128, 128, EE), 512>>>(g_w2h);
    combine_kernel <<<(N_TOK * (DD / 4)) / 256, 256>>>(x, out);
}

// round 16
// speedup vs baseline: 15.1031x; 8.1526x over previous
#include <cuda_runtime.h>
#include <cuda_bf16.h>
#include <math.h>
#include <cstdint>

#define N_TOK 8192
#define DD    1024
#define HH    2048
#define EE    8
#define NA    (N_TOK*2)
#define NA_PAD (NA+128)
#define RBLK  (N_TOK/8)

// ---------------- device scratch ----------------
__device__ float g_xn[(size_t)N_TOK*DD];
__device__ float g_h [(size_t)NA_PAD*HH];
__device__ float g_y [(size_t)NA*DD];
__device__ float g_gate[NA];
__device__ int   g_eid[NA];
__device__ int   g_counts[EE], g_offsets[EE], g_cursor[EE];
__device__ int   g_rows[NA];
__device__ float g_partials[RBLK*EE];

// ---------------- helpers ----------------
__device__ __forceinline__ uint32_t smem_u32(const void* p) {
    uint32_t a;
    asm("{ .reg .u64 t; cvta.to.shared.u64 t, %1; cvt.u32.u64 %0, t; }" : "=r"(a) : "l"(p));
    return a;
}
__device__ __forceinline__ void ldmx4(uint32_t* r, uint32_t addr) {
    asm volatile("ldmatrix.sync.aligned.m8n8.x4.shared.b16 {%0,%1,%2,%3}, [%4];"
        : "=r"(r[0]), "=r"(r[1]), "=r"(r[2]), "=r"(r[3]) : "r"(addr));
}
__device__ __forceinline__ void mma16816h(float* d, const uint32_t* a, const uint32_t* b) {
    asm volatile("mma.sync.aligned.m16n8k16.row.col.f32.f16.f16.f32 "
        "{%0,%1,%2,%3}, {%4,%5,%6,%7}, {%8,%9}, {%0,%1,%2,%3};"
        : "+f"(d[0]), "+f"(d[1]), "+f"(d[2]), "+f"(d[3])
        : "r"(a[0]), "r"(a[1]), "r"(a[2]), "r"(a[3]), "r"(b[0]), "r"(b[1]));
}
__device__ __forceinline__ uint32_t rnpackh(float fx, float fy) {
    uint32_t r;
    asm("cvt.rn.f16x2.f32 %0, %1, %2;" : "=r"(r) : "f"(fy), "f"(fx));
    return r;
}
__device__ __forceinline__ float gelu_exact(float v) {
    return 0.5f * v * (1.0f + erff(v * 0.70710678118654752f));
}

// ---------------- small kernels ----------------
__global__ void init_kernel() {
    int t = threadIdx.x;
    if (t < EE) { g_counts[t] = 0; g_cursor[t] = 0; }
}

__global__ void ln_kernel(const float* __restrict__ x,
                          const float* __restrict__ gamma,
                          const float* __restrict__ beta) {
    int t = blockIdx.x, tid = threadIdx.x;
    const float4* xr = (const float4*)(x + (size_t)t * DD);
    float4 v = xr[tid];
    float s = v.x + v.y + v.z + v.w;
    float ss = fmaf(v.x, v.x, fmaf(v.y, v.y, fmaf(v.z, v.z, v.w * v.w)));
    #pragma unroll
    for (int o = 16; o > 0; o >>= 1) {
        s  += __shfl_xor_sync(0xffffffffu, s,  o);
        ss += __shfl_xor_sync(0xffffffffu, ss, o);
    }
    __shared__ float shs[8], shss[8];
    int warp = tid >> 5, lane = tid & 31;
    if (lane == 0) { shs[warp] = s; shss[warp] = ss; }
    __syncthreads();
    __shared__ float mu_s, rstd_s;
    if (tid == 0) {
        float S = 0.f, SS = 0.f;
        #pragma unroll
        for (int w = 0; w < 8; w++) { S += shs[w]; SS += shss[w]; }
        float mu = S / (float)DD;
        mu_s = mu; rstd_s = rsqrtf(SS / (float)DD - mu * mu + 1e-5f);
    }
    __syncthreads();
    float mu = mu_s, rstd = rstd_s;
    float4 gv = ((const float4*)gamma)[tid];
    float4 bv = ((const float4*)beta)[tid];
    float4 o;
    o.x = (v.x - mu) * rstd * gv.x + bv.x;
    o.y = (v.y - mu) * rstd * gv.y + bv.y;
    o.z = (v.z - mu) * rstd * gv.z + bv.z;
    o.w = (v.w - mu) * rstd * gv.w + bv.w;
    ((float4*)(g_xn + (size_t)t * DD))[tid] = o;
}

__global__ void router_kernel(const float* __restrict__ gate_w) {
    __shared__ float gw[EE * DD];
    __shared__ float probs_sh[8][EE];
    int tid = threadIdx.x;
    #pragma unroll
    for (int p = 0; p < 8; p++)
        ((float4*)gw)[tid + p * 256] = ((const float4*)gate_w)[tid + p * 256];
    __syncthreads();
    int warp = tid >> 5, lane = tid & 31;
    int t = blockIdx.x * 8 + warp;
    const float4* xr = (const float4*)(g_xn + (size_t)t * DD);
    float acc[EE];
    #pragma unroll
    for (int e = 0; e < EE; e++) acc[e] = 0.f;
    #pragma unroll
    for (int c = 0; c < 8; c++) {
        float4 xv = xr[c * 32 + lane];
        #pragma unroll
        for (int e = 0; e < EE; e++) {
            float4 gv = ((const float4*)(gw + e * DD))[c * 32 + lane];
            acc[e] += xv.x * gv.x + xv.y * gv.y + xv.z * gv.z + xv.w * gv.w;
        }
    }
    #pragma unroll
    for (int o = 16; o > 0; o >>= 1)
        #pragma unroll
        for (int e = 0; e < EE; e++)
            acc[e] += __shfl_xor_sync(0xffffffffu, acc[e], o);
    if (lane == 0) {
        int i0 = 0; float v0 = acc[0];
        #pragma unroll
        for (int e = 1; e < EE; e++) if (acc[e] > v0) { v0 = acc[e]; i0 = e; }
        int i1 = -1; float v1 = -3.4e38f;
        #pragma unroll
        for (int e = 0; e < EE; e++) if (e != i0 && acc[e] > v1) { v1 = acc[e]; i1 = e; }
        float e10 = expf(v1 - v0);
        g_eid[2*t] = i0; g_eid[2*t+1] = i1;
        g_gate[2*t] = 1.f / (1.f + e10); g_gate[2*t+1] = e10 / (1.f + e10);
        atomicAdd(&g_counts[i0], 1);
        atomicAdd(&g_counts[i1], 1);
        float s = 0.f, p[EE];
        #pragma unroll
        for (int e = 0; e < EE; e++) { p[e] = expf(acc[e] - v0); s += p[e]; }
        float inv = 1.f / s;
        #pragma unroll
        for (int e = 0; e < EE; e++) probs_sh[warp][e] = p[e] * inv;
    }
    __syncthreads();
    if (tid < EE) {
        float s = 0.f;
        #pragma unroll
        for (int w = 0; w < 8; w++) s += probs_sh[w][tid];
        g_partials[blockIdx.x * EE + tid] = s;
    }
}

__global__ void finalize_kernel(float* __restrict__ d_out, int has_scalar) {
    __shared__ float avg[EE];
    int tid = threadIdx.x;
    int e = tid >> 5, lane = tid & 31;
    float s = 0.f;
    for (int b = lane; b < RBLK; b += 32) s += g_partials[b * EE + e];
    #pragma unroll
    for (int o = 16; o > 0; o >>= 1) s += __shfl_xor_sync(0xffffffffu, s, o);
    if (lane == 0) avg[e] = s / (float)N_TOK;
    __syncthreads();
    if (tid == 0) {
        int o = 0;
        #pragma unroll
        for (int q = 0; q < EE; q++) { g_offsets[q] = o; o += g_counts[q]; }
        if (has_scalar) {
            float m = 0.f;
            #pragma unroll
            for (int q = 0; q < EE; q++) m += avg[q];
            m /= (float)EE;
            float v = 0.f;
            #pragma unroll
            for (int q = 0; q < EE; q++) { float d = avg[q] - m; v += d * d; }
            v /= (float)(EE - 1);
            float r = sqrtf(v) / (m + 1e-6f);
            d_out[(size_t)N_TOK * DD] = r * r * 0.01f;
        }
    }
}

__global__ void place_kernel() {
    int a = blockIdx.x * 256 + threadIdx.x;
    if (a >= NA) return;
    int e = g_eid[a];
    int pos = atomicAdd(&g_cursor[e], 1);
    g_rows[g_offsets[e] + pos] = a;
}

// ---- grouped GEMM: 512 thr, k64 chunks, reg prefetch, in-loop fp16 convert ----
#define RSB 144            // bytes per 64-col fp16 row (128B data + 16B pad)
#define APL (128*RSB)      // 18432 bytes per plane
// planes: [A][B] = 2*APL = 36864 B static smem

// MODE 0: gemm1  A = gathered g_xn rows, B = w1[e], out = gelu -> g_h (fp32)
// MODE 1: gemm2  A = g_h rows,           B = w2[e], out = gate*acc -> g_y
template<int KTOT, int NROWS, int MODE>
__global__ __launch_bounds__(512)
void gemm_kernel(const float* __restrict__ W) {
    int e = blockIdx.z;
    int cnt = g_counts[e];
    int m0 = blockIdx.y * 128;
    if (m0 >= cnt) return;
    int off = g_offsets[e];
    int n0 = blockIdx.x * 128;

    __shared__ __align__(16) char smem[2 * APL];
    __shared__ const float* rowp[128];

    int tid = threadIdx.x, wid = tid >> 5, lane = tid & 31;
    int wm = wid >> 2, wn = wid & 3;          // 4x4 warp grid, warp tile 32x32
    int g = lane >> 2, ttg = lane & 3;

    if (tid < 128) {
        int r = m0 + tid;
        const float* p = nullptr;
        if (r < cnt) {
            if (MODE == 0) {
                int aid = g_rows[off + r];
                p = g_xn + (size_t)(aid >> 1) * DD;
            } else {
                p = g_h + (size_t)(off + r) * (size_t)KTOT;
            }
        }
        rowp[tid] = p;
    }
    __syncthreads();

    const float* Bbase = W + ((size_t)e * NROWS + n0) * (size_t)KTOT;
    uint32_t sb = smem_u32(smem);

    uint32_t a_addr = sb + (uint32_t)((wm * 32 + (lane & 15)) * RSB + (lane >> 4) * 16);
    uint32_t b_addr = sb + APL +
        (uint32_t)((wn * 32 + ((lane >> 4) << 3) + (lane & 7)) * RSB + ((lane >> 3) & 1) * 16);

    // staging: 8 float4 per thread (A: idx<2048, B: idx>=2048); 16 float4 per 64-f row
    int srow[8], sc4[8], sIsA[8];
    #pragma unroll
    for (int q = 0; q < 8; q++) {
        int idx = q * 512 + tid;
        int rem = idx & 2047;
        srow[q] = rem >> 4;
        sc4[q]  = (rem & 15) * 4;
        sIsA[q] = (idx < 2048);
    }

    float acc[2][4][4];
    #pragma unroll
    for (int a = 0; a < 2; a++)
        #pragma unroll
        for (int b = 0; b < 4; b++)
            #pragma unroll
            for (int c = 0; c < 4; c++) acc[a][b][c] = 0.f;

    // ---- prefetch chunk 0 into registers ----
    float4 pref[8];
    #pragma unroll
    for (int q = 0; q < 8; q++) {
        if (sIsA[q]) {
            const float* p = rowp[srow[q]];
            pref[q] = p ? *(const float4*)(p + sc4[q]) : make_float4(0.f, 0.f, 0.f, 0.f);
        } else {
            pref[q] = *(const float4*)(Bbase + (size_t)srow[q] * KTOT + sc4[q]);
        }
    }

    const int NCH = KTOT / 64;
    for (int c = 0; c < NCH; c++) {
        // ---- store prefetched regs -> fp16 planes ----
        #pragma unroll
        for (int q = 0; q < 8; q++) {
            uint32_t doff = (uint32_t)(srow[q] * RSB + sc4[q] * 2);
            char* pl = smem + (sIsA[q] ? 0 : APL);
            uint32_t p0 = rnpackh(pref[q].x, pref[q].y);
            uint32_t p1 = rnpackh(pref[q].z, pref[q].w);
            *(uint2*)(pl + doff) = make_uint2(p0, p1);
        }
        __syncthreads();

        // ---- issue next chunk's global loads (latency hidden by mma below) ----
        if (c + 1 < NCH) {
            int k0n = (c + 1) * 64;
            #pragma unroll
            for (int q = 0; q < 8; q++) {
                if (sIsA[q]) {
                    const float* p = rowp[srow[q]];
                    pref[q] = p ? *(const float4*)(p + k0n + sc4[q])
                                : make_float4(0.f, 0.f, 0.f, 0.f);
                } else {
                    pref[q] = *(const float4*)(Bbase + (size_t)srow[q] * KTOT + k0n + sc4[q]);
                }
            }
        }

        // ---- compute: 4 k16 steps from smem ----
        #pragma unroll
        for (int ks = 0; ks < 4; ks++) {
            uint32_t ah[2][4], bh[4][2];
            #pragma unroll
            for (int mt = 0; mt < 2; mt++)
                ldmx4(ah[mt], a_addr + mt * (16 * RSB) + ks * 32);
            #pragma unroll
            for (int p = 0; p < 2; p++) {
                uint32_t r[4];
                ldmx4(r, b_addr + p * (16 * RSB) + ks * 32);
                bh[2*p][0] = r[0]; bh[2*p][1] = r[1];
                bh[2*p+1][0] = r[2]; bh[2*p+1][1] = r[3];
            }
            #pragma unroll
            for (int mt = 0; mt < 2; mt++)
                #pragma unroll
                for (int nt = 0; nt < 4; nt++)
                    mma16816h(acc[mt][nt], ah[mt], bh[nt]);
        }
        __syncthreads();
    }

    // ---- epilogue ----
    int t2 = ttg * 2;
    #pragma unroll
    for (int mt = 0; mt < 2; mt++) {
        int r0 = m0 + wm * 32 + mt * 16 + g;
        int r1 = r0 + 8;
        bool v0 = r0 < cnt, v1 = r1 < cnt;
        float gate0 = 0.f, gate1 = 0.f;
        int aid0 = 0, aid1 = 0;
        if (MODE == 1) {
            if (v0) { aid0 = g_rows[off + r0]; gate0 = g_gate[aid0]; }
            if (v1) { aid1 = g_rows[off + r1]; gate1 = g_gate[aid1]; }
        }
        #pragma unroll
        for (int nt = 0; nt < 4; nt++) {
            int col = n0 + wn * 32 + nt * 8 + t2;
            float c0 = acc[mt][nt][0], c1 = acc[mt][nt][1];
            float c2 = acc[mt][nt][2], c3 = acc[mt][nt][3];
            if (MODE == 0) {
                if (v0) {
                    float2 o; o.x = gelu_exact(c0); o.y = gelu_exact(c1);
                    *(float2*)(g_h + (size_t)(off + r0) * HH + col) = o;
                }
                if (v1) {
                    float2 o; o.x = gelu_exact(c2); o.y = gelu_exact(c3);
                    *(float2*)(g_h + (size_t)(off + r1) * HH + col) = o;
                }
            } else {
                if (v0) {
                    float2 o; o.x = c0 * gate0; o.y = c1 * gate0;
                    *(float2*)(g_y + (size_t)aid0 * DD + col) = o;
                }
                if (v1) {
                    float2 o; o.x = c2 * gate1; o.y = c3 * gate1;
                    *(float2*)(g_y + (size_t)aid1 * DD + col) = o;
                }
            }
        }
    }
}

// ---------------- combine ----------------
__global__ void combine_kernel(const float* __restrict__ x, float* __restrict__ out) {
    size_t idx = (size_t)blockIdx.x * 256 + threadIdx.x;
    int t = (int)(idx / (DD / 4));
    int dv = (int)(idx % (DD / 4));
    float4 xv = ((const float4*)x)[idx];
    float4 y0 = ((const float4*)(g_y + (size_t)(2 * t)     * DD))[dv];
    float4 y1 = ((const float4*)(g_y + (size_t)(2 * t + 1) * DD))[dv];
    float4 o;
    o.x = xv.x + y0.x + y1.x;
    o.y = xv.y + y0.y + y1.y;
    o.z = xv.z + y0.z + y1.z;
    o.w = xv.w + y0.w + y1.w;
    ((float4*)out)[idx] = o;
}

// ---------------- launch ----------------
extern "C" void kernel_launch(void* const* d_in, const int* in_sizes, int n_in,
                              void* d_out, int out_size) {
    const float* x      = (const float*)d_in[0];
    const float* gate_w = (const float*)d_in[1];
    const float* w1     = (const float*)d_in[2];
    const float* w2     = (const float*)d_in[3];
    const float* gamma  = (const float*)d_in[4];
    const float* beta   = (const float*)d_in[5];
    float* out = (float*)d_out;
    int has_scalar = (out_size > N_TOK * DD) ? 1 : 0;

    init_kernel    <<<1, 32>>>();
    ln_kernel      <<<N_TOK, 256>>>(x, gamma, beta);
    router_kernel  <<<RBLK, 256>>>(gate_w);
    finalize_kernel<<<1, 256>>>(out, has_scalar);
    place_kernel   <<<NA / 256, 256>>>();
    gemm_kernel<DD, HH, 0><<<dim3(HH / 128, 128, EE), 512>>>(w1);
    gemm_kernel<HH, DD, 1><<<dim3(DD / 128, 128, EE), 512>>>(w2);
    combine_kernel <<<(N_TOK * (DD / 4)) / 256, 256>>>(x, out);
}

// round 17
// speedup vs baseline: 15.6903x; 1.0389x over previous
#include <cuda_runtime.h>
#include <cuda_fp16.h>
#include <math.h>
#include <cstdint>

#define N_TOK 8192
#define DD    1024
#define HH    2048
#define EE    8
#define NA    (N_TOK*2)
#define NA_PAD (NA+128)
#define RBLK  (N_TOK/8)

// ---------------- device scratch ----------------
__device__ float  g_xn[(size_t)N_TOK*DD];
__device__ float  g_h [(size_t)NA_PAD*HH];
__device__ __half g_w1h[(size_t)EE*HH*DD];
__device__ __half g_w2h[(size_t)EE*DD*HH];
__device__ float  g_y [(size_t)NA*DD];
__device__ float  g_gate[NA];
__device__ int    g_eid[NA];
__device__ int    g_counts[EE], g_offsets[EE], g_cursor[EE];
__device__ int    g_rows[NA];
__device__ float  g_partials[RBLK*EE];

// ---------------- helpers ----------------
__device__ __forceinline__ uint32_t smem_u32(const void* p) {
    uint32_t a;
    asm("{ .reg .u64 t; cvta.to.shared.u64 t, %1; cvt.u32.u64 %0, t; }" : "=r"(a) : "l"(p));
    return a;
}
__device__ __forceinline__ void ldmx4(uint32_t* r, uint32_t addr) {
    asm volatile("ldmatrix.sync.aligned.m8n8.x4.shared.b16 {%0,%1,%2,%3}, [%4];"
        : "=r"(r[0]), "=r"(r[1]), "=r"(r[2]), "=r"(r[3]) : "r"(addr));
}
__device__ __forceinline__ void mma16816h(float* d, const uint32_t* a, const uint32_t* b) {
    asm volatile("mma.sync.aligned.m16n8k16.row.col.f32.f16.f16.f32 "
        "{%0,%1,%2,%3}, {%4,%5,%6,%7}, {%8,%9}, {%0,%1,%2,%3};"
        : "+f"(d[0]), "+f"(d[1]), "+f"(d[2]), "+f"(d[3])
        : "r"(a[0]), "r"(a[1]), "r"(a[2]), "r"(a[3]), "r"(b[0]), "r"(b[1]));
}
__device__ __forceinline__ uint32_t rnpackh(float fx, float fy) {
    uint32_t r;
    asm("cvt.rn.f16x2.f32 %0, %1, %2;" : "=r"(r) : "f"(fy), "f"(fx));
    return r;
}
__device__ __forceinline__ float gelu_exact(float v) {
    return 0.5f * v * (1.0f + erff(v * 0.70710678118654752f));
}

// ---------------- small kernels ----------------
__global__ void init_kernel() {
    int t = threadIdx.x;
    if (t < EE) { g_counts[t] = 0; g_cursor[t] = 0; }
}

__global__ void ln_kernel(const float* __restrict__ x,
                          const float* __restrict__ gamma,
                          const float* __restrict__ beta) {
    int t = blockIdx.x, tid = threadIdx.x;
    const float4* xr = (const float4*)(x + (size_t)t * DD);
    float4 v = xr[tid];
    float s = v.x + v.y + v.z + v.w;
    float ss = fmaf(v.x, v.x, fmaf(v.y, v.y, fmaf(v.z, v.z, v.w * v.w)));
    #pragma unroll
    for (int o = 16; o > 0; o >>= 1) {
        s  += __shfl_xor_sync(0xffffffffu, s,  o);
        ss += __shfl_xor_sync(0xffffffffu, ss, o);
    }
    __shared__ float shs[8], shss[8];
    int warp = tid >> 5, lane = tid & 31;
    if (lane == 0) { shs[warp] = s; shss[warp] = ss; }
    __syncthreads();
    __shared__ float mu_s, rstd_s;
    if (tid == 0) {
        float S = 0.f, SS = 0.f;
        #pragma unroll
        for (int w = 0; w < 8; w++) { S += shs[w]; SS += shss[w]; }
        float mu = S / (float)DD;
        mu_s = mu; rstd_s = rsqrtf(SS / (float)DD - mu * mu + 1e-5f);
    }
    __syncthreads();
    float mu = mu_s, rstd = rstd_s;
    float4 gv = ((const float4*)gamma)[tid];
    float4 bv = ((const float4*)beta)[tid];
    float4 o;
    o.x = (v.x - mu) * rstd * gv.x + bv.x;
    o.y = (v.y - mu) * rstd * gv.y + bv.y;
    o.z = (v.z - mu) * rstd * gv.z + bv.z;
    o.w = (v.w - mu) * rstd * gv.w + bv.w;
    ((float4*)(g_xn + (size_t)t * DD))[tid] = o;
}

// fp32 -> fp16 weights (one float4 per thread); dst selected by flag
__global__ void convh_kernel(const float* __restrict__ src, int which) {
    __half* dst = which ? g_w2h : g_w1h;
    size_t i = (size_t)blockIdx.x * 256 + threadIdx.x;
    float4 v = ((const float4*)src)[i];
    uint2 hp;
    hp.x = rnpackh(v.x, v.y);
    hp.y = rnpackh(v.z, v.w);
    *(uint2*)(dst + i * 4) = hp;
}

__global__ void router_kernel(const float* __restrict__ gate_w) {
    __shared__ float gw[EE * DD];
    __shared__ float probs_sh[8][EE];
    int tid = threadIdx.x;
    #pragma unroll
    for (int p = 0; p < 8; p++)
        ((float4*)gw)[tid + p * 256] = ((const float4*)gate_w)[tid + p * 256];
    __syncthreads();
    int warp = tid >> 5, lane = tid & 31;
    int t = blockIdx.x * 8 + warp;
    const float4* xr = (const float4*)(g_xn + (size_t)t * DD);
    float acc[EE];
    #pragma unroll
    for (int e = 0; e < EE; e++) acc[e] = 0.f;
    #pragma unroll
    for (int c = 0; c < 8; c++) {
        float4 xv = xr[c * 32 + lane];
        #pragma unroll
        for (int e = 0; e < EE; e++) {
            float4 gv = ((const float4*)(gw + e * DD))[c * 32 + lane];
            acc[e] += xv.x * gv.x + xv.y * gv.y + xv.z * gv.z + xv.w * gv.w;
        }
    }
    #pragma unroll
    for (int o = 16; o > 0; o >>= 1)
        #pragma unroll
        for (int e = 0; e < EE; e++)
            acc[e] += __shfl_xor_sync(0xffffffffu, acc[e], o);
    if (lane == 0) {
        int i0 = 0; float v0 = acc[0];
        #pragma unroll
        for (int e = 1; e < EE; e++) if (acc[e] > v0) { v0 = acc[e]; i0 = e; }
        int i1 = -1; float v1 = -3.4e38f;
        #pragma unroll
        for (int e = 0; e < EE; e++) if (e != i0 && acc[e] > v1) { v1 = acc[e]; i1 = e; }
        float e10 = expf(v1 - v0);
        g_eid[2*t] = i0; g_eid[2*t+1] = i1;
        g_gate[2*t] = 1.f / (1.f + e10); g_gate[2*t+1] = e10 / (1.f + e10);
        atomicAdd(&g_counts[i0], 1);
        atomicAdd(&g_counts[i1], 1);
        float s = 0.f, p[EE];
        #pragma unroll
        for (int e = 0; e < EE; e++) { p[e] = expf(acc[e] - v0); s += p[e]; }
        float inv = 1.f / s;
        #pragma unroll
        for (int e = 0; e < EE; e++) probs_sh[warp][e] = p[e] * inv;
    }
    __syncthreads();
    if (tid < EE) {
        float s = 0.f;
        #pragma unroll
        for (int w = 0; w < 8; w++) s += probs_sh[w][tid];
        g_partials[blockIdx.x * EE + tid] = s;
    }
}

__global__ void finalize_kernel(float* __restrict__ d_out, int has_scalar) {
    __shared__ float avg[EE];
    int tid = threadIdx.x;
    int e = tid >> 5, lane = tid & 31;
    float s = 0.f;
    for (int b = lane; b < RBLK; b += 32) s += g_partials[b * EE + e];
    #pragma unroll
    for (int o = 16; o > 0; o >>= 1) s += __shfl_xor_sync(0xffffffffu, s, o);
    if (lane == 0) avg[e] = s / (float)N_TOK;
    __syncthreads();
    if (tid == 0) {
        int o = 0;
        #pragma unroll
        for (int q = 0; q < EE; q++) { g_offsets[q] = o; o += g_counts[q]; }
        if (has_scalar) {
            float m = 0.f;
            #pragma unroll
            for (int q = 0; q < EE; q++) m += avg[q];
            m /= (float)EE;
            float v = 0.f;
            #pragma unroll
            for (int q = 0; q < EE; q++) { float d = avg[q] - m; v += d * d; }
            v /= (float)(EE - 1);
            float r = sqrtf(v) / (m + 1e-6f);
            d_out[(size_t)N_TOK * DD] = r * r * 0.01f;
        }
    }
}

__global__ void place_kernel() {
    int a = blockIdx.x * 256 + threadIdx.x;
    if (a >= NA) return;
    int e = g_eid[a];
    int pos = atomicAdd(&g_cursor[e], 1);
    g_rows[g_offsets[e] + pos] = a;
}

// ---- grouped GEMM: 512 thr, k64, A fp32 in-loop convert, B fp16 pre-converted ----
#define RSB 144            // bytes per 64-col fp16 row (128B data + 16B pad)
#define APL (128*RSB)      // 18432 bytes per plane
// planes: [A][B] = 2*APL = 36864 B static smem

// MODE 0: gemm1  A = gathered g_xn rows, B = g_w1h, out = gelu -> g_h (fp32)
// MODE 1: gemm2  A = g_h rows,           B = g_w2h, out = gate*acc -> g_y
template<int KTOT, int NROWS, int MODE>
__global__ __launch_bounds__(512)
void gemm_kernel() {
    int e = blockIdx.z;
    int cnt = g_counts[e];
    int m0 = blockIdx.y * 128;
    if (m0 >= cnt) return;
    int off = g_offsets[e];
    int n0 = blockIdx.x * 128;

    __shared__ __align__(16) char smem[2 * APL];
    __shared__ const float* rowp[128];

    int tid = threadIdx.x, wid = tid >> 5, lane = tid & 31;
    int wm = wid >> 2, wn = wid & 3;          // 4x4 warp grid, warp tile 32x32
    int g = lane >> 2, ttg = lane & 3;

    if (tid < 128) {
        int r = m0 + tid;
        const float* p = nullptr;
        if (r < cnt) {
            if (MODE == 0) {
                int aid = g_rows[off + r];
                p = g_xn + (size_t)(aid >> 1) * DD;
            } else {
                p = g_h + (size_t)(off + r) * (size_t)KTOT;
            }
        }
        rowp[tid] = p;
    }
    __syncthreads();

    const __half* Bbase = (MODE ? g_w2h : g_w1h)
                        + ((size_t)e * NROWS + n0) * (size_t)KTOT;
    uint32_t sb = smem_u32(smem);

    uint32_t a_addr = sb + (uint32_t)((wm * 32 + (lane & 15)) * RSB + (lane >> 4) * 16);
    uint32_t b_addr = sb + APL +
        (uint32_t)((wn * 32 + ((lane >> 4) << 3) + (lane & 7)) * RSB + ((lane >> 3) & 1) * 16);

    // A staging: 4 float4 per thread (2048 f4 total); 16 f4 per 64-col row
    int srow[4], sc4[4];
    #pragma unroll
    for (int q = 0; q < 4; q++) {
        int idx = q * 512 + tid;
        srow[q] = idx >> 4;
        sc4[q]  = (idx & 15) * 4;
    }
    // B staging: 2 uint4 per thread (1024 16B-units total); 8 units per row
    int brow[2], bc16[2];
    #pragma unroll
    for (int q = 0; q < 2; q++) {
        int idx = q * 512 + tid;
        brow[q] = idx >> 3;
        bc16[q] = idx & 7;
    }

    float acc[2][4][4];
    #pragma unroll
    for (int a = 0; a < 2; a++)
        #pragma unroll
        for (int b = 0; b < 4; b++)
            #pragma unroll
            for (int c = 0; c < 4; c++) acc[a][b][c] = 0.f;

    // ---- prefetch chunk 0 into registers ----
    float4 prefA[4];
    uint4  prefB[2];
    #pragma unroll
    for (int q = 0; q < 4; q++) {
        const float* p = rowp[srow[q]];
        prefA[q] = p ? *(const float4*)(p + sc4[q]) : make_float4(0.f, 0.f, 0.f, 0.f);
    }
    #pragma unroll
    for (int q = 0; q < 2; q++)
        prefB[q] = *(const uint4*)(Bbase + (size_t)brow[q] * KTOT + bc16[q] * 8);

    const int NCH = KTOT / 64;
    for (int c = 0; c < NCH; c++) {
        // ---- store prefetched regs -> planes ----
        #pragma unroll
        for (int q = 0; q < 4; q++) {
            uint32_t p0 = rnpackh(prefA[q].x, prefA[q].y);
            uint32_t p1 = rnpackh(prefA[q].z, prefA[q].w);
            *(uint2*)(smem + srow[q] * RSB + sc4[q] * 2) = make_uint2(p0, p1);
        }
        #pragma unroll
        for (int q = 0; q < 2; q++)
            *(uint4*)(smem + APL + brow[q] * RSB + bc16[q] * 16) = prefB[q];
        __syncthreads();

        // ---- issue next chunk's global loads (latency hidden by mma below) ----
        if (c + 1 < NCH) {
            int k0n = (c + 1) * 64;
            #pragma unroll
            for (int q = 0; q < 4; q++) {
                const float* p = rowp[srow[q]];
                prefA[q] = p ? *(const float4*)(p + k0n + sc4[q])
                             : make_float4(0.f, 0.f, 0.f, 0.f);
            }
            #pragma unroll
            for (int q = 0; q < 2; q++)
                prefB[q] = *(const uint4*)(Bbase + (size_t)brow[q] * KTOT + k0n + bc16[q] * 8);
        }

        // ---- compute: 4 k16 steps from smem ----
        #pragma unroll
        for (int ks = 0; ks < 4; ks++) {
            uint32_t ah[2][4], bh[4][2];
            #pragma unroll
            for (int mt = 0; mt < 2; mt++)
                ldmx4(ah[mt], a_addr + mt * (16 * RSB) + ks * 32);
            #pragma unroll
            for (int p = 0; p < 2; p++) {
                uint32_t r[4];
                ldmx4(r, b_addr + p * (16 * RSB) + ks * 32);
                bh[2*p][0] = r[0]; bh[2*p][1] = r[1];
                bh[2*p+1][0] = r[2]; bh[2*p+1][1] = r[3];
            }
            #pragma unroll
            for (int mt = 0; mt < 2; mt++)
                #pragma unroll
                for (int nt = 0; nt < 4; nt++)
                    mma16816h(acc[mt][nt], ah[mt], bh[nt]);
        }
        __syncthreads();
    }

    // ---- epilogue ----
    int t2 = ttg * 2;
    #pragma unroll
    for (int mt = 0; mt < 2; mt++) {
        int r0 = m0 + wm * 32 + mt * 16 + g;
        int r1 = r0 + 8;
        bool v0 = r0 < cnt, v1 = r1 < cnt;
        float gate0 = 0.f, gate1 = 0.f;
        int aid0 = 0, aid1 = 0;
        if (MODE == 1) {
            if (v0) { aid0 = g_rows[off + r0]; gate0 = g_gate[aid0]; }
            if (v1) { aid1 = g_rows[off + r1]; gate1 = g_gate[aid1]; }
        }
        #pragma unroll
        for (int nt = 0; nt < 4; nt++) {
            int col = n0 + wn * 32 + nt * 8 + t2;
            float c0 = acc[mt][nt][0], c1 = acc[mt][nt][1];
            float c2 = acc[mt][nt][2], c3 = acc[mt][nt][3];
            if (MODE == 0) {
                if (v0) {
                    float2 o; o.x = gelu_exact(c0); o.y = gelu_exact(c1);
                    *(float2*)(g_h + (size_t)(off + r0) * HH + col) = o;
                }
                if (v1) {
                    float2 o; o.x = gelu_exact(c2); o.y = gelu_exact(c3);
                    *(float2*)(g_h + (size_t)(off + r1) * HH + col) = o;
                }
            } else {
                if (v0) {
                    float2 o; o.x = c0 * gate0; o.y = c1 * gate0;
                    *(float2*)(g_y + (size_t)aid0 * DD + col) = o;
                }
                if (v1) {
                    float2 o; o.x = c2 * gate1; o.y = c3 * gate1;
                    *(float2*)(g_y + (size_t)aid1 * DD + col) = o;
                }
            }
        }
    }
}

// ---------------- combine ----------------
__global__ void combine_kernel(const float* __restrict__ x, float* __restrict__ out) {
    size_t idx = (size_t)blockIdx.x * 256 + threadIdx.x;
    int t = (int)(idx / (DD / 4));
    int dv = (int)(idx % (DD / 4));
    float4 xv = ((const float4*)x)[idx];
    float4 y0 = ((const float4*)(g_y + (size_t)(2 * t)     * DD))[dv];
    float4 y1 = ((const float4*)(g_y + (size_t)(2 * t + 1) * DD))[dv];
    float4 o;
    o.x = xv.x + y0.x + y1.x;
    o.y = xv.y + y0.y + y1.y;
    o.z = xv.z + y0.z + y1.z;
    o.w = xv.w + y0.w + y1.w;
    ((float4*)out)[idx] = o;
}

// ---------------- launch ----------------
extern "C" void kernel_launch(void* const* d_in, const int* in_sizes, int n_in,
                              void* d_out, int out_size) {
    const float* x      = (const float*)d_in[0];
    const float* gate_w = (const float*)d_in[1];
    const float* w1     = (const float*)d_in[2];
    const float* w2     = (const float*)d_in[3];
    const float* gamma  = (const float*)d_in[4];
    const float* beta   = (const float*)d_in[5];
    float* out = (float*)d_out;
    int has_scalar = (out_size > N_TOK * DD) ? 1 : 0;

    init_kernel    <<<1, 32>>>();
    ln_kernel      <<<N_TOK, 256>>>(x, gamma, beta);
    convh_kernel   <<<(EE*(size_t)HH*DD/4)/256, 256>>>(w1, 0);
    convh_kernel   <<<(EE*(size_t)DD*HH/4)/256, 256>>>(w2, 1);
    router_kernel  <<<RBLK, 256>>>(gate_w);
    finalize_kernel<<<1, 256>>>(out, has_scalar);
    place_kernel   <<<NA / 256, 256>>>();
    gemm_kernel<DD, HH, 0><<<dim3(HH / 128, 128, EE), 512>>>();
    gemm_kernel<HH, DD, 1><<<dim3(DD / 128, 128, EE), 512>>>();
    combine_kernel <<<(N_TOK * (DD / 4)) / 256, 256>>>(x, out);
}